// round 1
// baseline (speedup 1.0000x reference)
#include <cuda_runtime.h>
#include <cuda_bf16.h>
#include <cstdint>

// Problem constants (shape-fixed per reference)
#define NMAX 50048
#define EMAX 400000

// Scratch (device globals: allocation-free rule)
__device__ float g_msgs[(size_t)EMAX * 128];
__device__ float g_gate[EMAX];
__device__ float g_wexp[EMAX];
__device__ int   g_segmax[NMAX];
__device__ float g_denom[NMAX];
__device__ float g_aggr[(size_t)NMAX * 128];

// ---------- float ordered-int encoding for atomicMax on floats ----------
__device__ __forceinline__ int f2ord(float f) {
    int i = __float_as_int(f);
    return (i >= 0) ? i : (i ^ 0x7fffffff);
}
__device__ __forceinline__ float ord2f(int o) {
    return __int_as_float((o >= 0) ? o : (o ^ 0x7fffffff));
}

// ---------------------------------------------------------------------------
// Generic tile MLP layer: sOut[64][NOUT] = act(sIn[64][K] @ W[K][NOUT] + B)
// Block = 256 threads; thread (tx = tid&31, ty = tid>>5) computes
// 8 edges (rows e = ty*8+i) x NJ*? outputs (cols o = tx + 32*j).
// Weights staged through smem in K-slabs of 8 rows.
// ---------------------------------------------------------------------------
template<int K, int NJ, bool RELU>
__device__ __forceinline__ void mlp_layer(
    const float* __restrict__ W, const float* __restrict__ B,
    const float* sIn, int ldin, float* sOut, int ldout, float* sW)
{
    const int NOUT = NJ * 32;
    const int tid = threadIdx.x;
    const int tx = tid & 31;
    const int ty = tid >> 5;

    float acc[8][NJ];
#pragma unroll
    for (int i = 0; i < 8; i++)
#pragma unroll
        for (int j = 0; j < NJ; j++) acc[i][j] = 0.f;

    for (int kc = 0; kc < K; kc += 8) {
        __syncthreads();   // protect sW against previous-slab readers
        // stage W[kc..kc+7][0..NOUT) into sW  (8*NOUT floats, float4 loads)
        {
            const float4* src = (const float4*)(W + (size_t)kc * NOUT);
            float4* dst = (float4*)sW;
            const int nvec = 8 * NOUT / 4;
            for (int t = tid; t < nvec; t += 256) dst[t] = src[t];
        }
        __syncthreads();
#pragma unroll
        for (int kk = 0; kk < 8; kk++) {
            float a[8];
#pragma unroll
            for (int i = 0; i < 8; i++)
                a[i] = sIn[(ty * 8 + i) * ldin + kc + kk];   // warp-broadcast
#pragma unroll
            for (int j = 0; j < NJ; j++) {
                float w = sW[kk * NOUT + tx + 32 * j];        // conflict-free
#pragma unroll
                for (int i = 0; i < 8; i++)
                    acc[i][j] += a[i] * w;
            }
        }
    }
    // epilogue: bias (+relu), write to sOut
#pragma unroll
    for (int j = 0; j < NJ; j++) {
        float bias = __ldg(B + tx + 32 * j);
#pragma unroll
        for (int i = 0; i < 8; i++) {
            float v = acc[i][j] + bias;
            if (RELU) v = fmaxf(v, 0.f);
            sOut[(ty * 8 + i) * ldout + tx + 32 * j] = v;
        }
    }
    __syncthreads();
}

// ---------------------------------------------------------------------------
// Kernel 1: init scratch
// ---------------------------------------------------------------------------
__global__ void init_kernel(int N) {
    int idx = blockIdx.x * blockDim.x + threadIdx.x;
    int total = N * 128;
    if (idx < total) g_aggr[idx] = 0.f;
    if (idx < N) {
        g_denom[idx] = 0.f;
        g_segmax[idx] = int(0x80000000);
    }
}

// ---------------------------------------------------------------------------
// Kernel 2: fused edge-MLP + gate-MLP.  64 edges / block, 256 threads.
// smem layout: sA[64*272] | sB[64*256] | sW[8*256]
// ---------------------------------------------------------------------------
__global__ __launch_bounds__(256)
void edge_kernel(
    const float* __restrict__ nodes, const float* __restrict__ edges,
    const int* __restrict__ senders, const int* __restrict__ receivers,
    const float* __restrict__ w1, const float* __restrict__ b1,
    const float* __restrict__ w2, const float* __restrict__ b2,
    const float* __restrict__ w3, const float* __restrict__ b3,
    const float* __restrict__ aw1, const float* __restrict__ ab1,
    const float* __restrict__ aw2, const float* __restrict__ ab2,
    const float* __restrict__ aw3, const float* __restrict__ ab3,
    int E)
{
    extern __shared__ float smem[];
    float* sA = smem;                 // 64*272
    float* sB = sA + 64 * 272;        // 64*256
    float* sW = sB + 64 * 256;        // 8*256

    const int tid = threadIdx.x;
    const int tx = tid & 31;
    const int ty = tid >> 5;
    const int e0 = blockIdx.x * 64;

    // ---- gather feats = [edge(16) | nodes[s](128) | nodes[r](128)] ----
#pragma unroll
    for (int i = 0; i < 8; i++) {
        int e = ty * 8 + i;
        int eg = e0 + e;
        int egc = eg < E ? eg : E - 1;
        int s = senders[egc];
        int r = receivers[egc];
        float* dst = sA + e * 272;
        if (tx < 4)
            *(float4*)(dst + tx * 4) = *(const float4*)(edges + (size_t)egc * 16 + tx * 4);
        *(float4*)(dst + 16 + tx * 4)  = *(const float4*)(nodes + (size_t)s * 128 + tx * 4);
        *(float4*)(dst + 144 + tx * 4) = *(const float4*)(nodes + (size_t)r * 128 + tx * 4);
    }
    // (mlp_layer's first __syncthreads orders the gather)

    // ---- message MLP ----
    mlp_layer<272, 8, true >(w1, b1, sA, 272, sB, 256, sW);  // h1
    mlp_layer<256, 8, false>(w2, b2, sB, 256, sA, 272, sW);  // h2 (in sA, stride 272)
    mlp_layer<256, 4, false>(w3, b3, sA, 272, sB, 128, sW);  // msgs (in sB, stride 128)

    // ---- flush msgs to global ----
    {
        const float4* src = (const float4*)sB;
        float4* dst = (float4*)(g_msgs + (size_t)e0 * 128);
        for (int t = tid; t < 64 * 128 / 4; t += 256) {
            int e = t >> 5;                   // 32 float4 per row
            if (e0 + e < E) dst[t] = src[t];
        }
    }

    // ---- gate MLP ----
    mlp_layer<128, 4, true >(aw1, ab1, sB, 128, sA, 128, sW); // g1 (in sA)
    mlp_layer<128, 4, false>(aw2, ab2, sA, 128, sB, 128, sW); // g2 (in sB)

    // gate = g2 @ aw3 + ab3  (128 -> 1), one warp per 8 edges
#pragma unroll
    for (int i = 0; i < 8; i++) {
        int e = ty * 8 + i;
        float p = 0.f;
#pragma unroll
        for (int j = 0; j < 4; j++)
            p += sB[e * 128 + tx + 32 * j] * __ldg(aw3 + tx + 32 * j);
#pragma unroll
        for (int off = 16; off > 0; off >>= 1)
            p += __shfl_xor_sync(0xffffffffu, p, off);
        if (tx == 0) {
            int eg = e0 + e;
            if (eg < E) {
                float gate = p + __ldg(ab3);
                g_gate[eg] = gate;
                int r = receivers[eg];
                atomicMax(&g_segmax[r], f2ord(gate));
            }
        }
    }
}

// ---------------------------------------------------------------------------
// Kernel 3: w = exp(gate - segmax[recv]); denom[recv] += w
// ---------------------------------------------------------------------------
__global__ void softmax_kernel(const int* __restrict__ receivers, int E) {
    int e = blockIdx.x * blockDim.x + threadIdx.x;
    if (e >= E) return;
    int r = receivers[e];
    float m = ord2f(g_segmax[r]);
    float w = expf(g_gate[e] - m);
    g_wexp[e] = w;
    atomicAdd(&g_denom[r], w);
}

// ---------------------------------------------------------------------------
// Kernel 4: aggr[recv] += (w/denom[recv]) * msgs[e]   (warp per edge)
// ---------------------------------------------------------------------------
__global__ __launch_bounds__(256)
void aggr_kernel(const int* __restrict__ receivers, int E) {
    int warp = (blockIdx.x * blockDim.x + threadIdx.x) >> 5;
    int lane = threadIdx.x & 31;
    if (warp >= E) return;
    int r = receivers[warp];
    float attn = g_wexp[warp] / g_denom[r];
    float4 v = *(const float4*)(g_msgs + (size_t)warp * 128 + lane * 4);
    float* dst = g_aggr + (size_t)r * 128 + lane * 4;
    atomicAdd(dst + 0, attn * v.x);
    atomicAdd(dst + 1, attn * v.y);
    atomicAdd(dst + 2, attn * v.z);
    atomicAdd(dst + 3, attn * v.w);
}

// ---------------------------------------------------------------------------
// Kernel 5: node update MLP.  64 nodes / block.
// smem: sA[64*256] | sB[64*256] | sW[8*256]
// ---------------------------------------------------------------------------
__global__ __launch_bounds__(256)
void node_kernel(
    const float* __restrict__ nodes,
    const float* __restrict__ uw1, const float* __restrict__ ub1,
    const float* __restrict__ uw2, const float* __restrict__ ub2,
    const float* __restrict__ uw3, const float* __restrict__ ub3,
    float* __restrict__ out, int N)
{
    extern __shared__ float smem[];
    float* sA = smem;                 // 64*256
    float* sB = sA + 64 * 256;        // 64*256
    float* sW = sB + 64 * 256;        // 8*256

    const int tid = threadIdx.x;
    const int tx = tid & 31;
    const int ty = tid >> 5;
    const int n0 = blockIdx.x * 64;

    // gather u = [node(128) | aggr(128)]
#pragma unroll
    for (int i = 0; i < 8; i++) {
        int e = ty * 8 + i;
        int n = n0 + e;
        float* dst = sA + e * 256;
        if (n < N) {
            *(float4*)(dst + tx * 4)       = *(const float4*)(nodes + (size_t)n * 128 + tx * 4);
            *(float4*)(dst + 128 + tx * 4) = *(const float4*)(g_aggr + (size_t)n * 128 + tx * 4);
        } else {
            float4 z = make_float4(0.f, 0.f, 0.f, 0.f);
            *(float4*)(dst + tx * 4) = z;
            *(float4*)(dst + 128 + tx * 4) = z;
        }
    }

    mlp_layer<256, 8, true >(uw1, ub1, sA, 256, sB, 256, sW);
    mlp_layer<256, 8, false>(uw2, ub2, sB, 256, sA, 256, sW);
    mlp_layer<256, 4, false>(uw3, ub3, sA, 256, sB, 128, sW);

    // store out rows (guarded)
    {
        const float4* src = (const float4*)sB;
        float4* dst = (float4*)(out + (size_t)n0 * 128);
        for (int t = tid; t < 64 * 128 / 4; t += 256) {
            int e = t >> 5;
            if (n0 + e < N) dst[t] = src[t];
        }
    }
}

// ---------------------------------------------------------------------------
extern "C" void kernel_launch(void* const* d_in, const int* in_sizes, int n_in,
                              void* d_out, int out_size)
{
    const float* nodes     = (const float*)d_in[0];
    const float* edges     = (const float*)d_in[1];
    const int*   senders   = (const int*)  d_in[2];
    const int*   receivers = (const int*)  d_in[3];
    const float* mw1 = (const float*)d_in[4];  const float* mb1 = (const float*)d_in[5];
    const float* mw2 = (const float*)d_in[6];  const float* mb2 = (const float*)d_in[7];
    const float* mw3 = (const float*)d_in[8];  const float* mb3 = (const float*)d_in[9];
    const float* aw1 = (const float*)d_in[10]; const float* ab1 = (const float*)d_in[11];
    const float* aw2 = (const float*)d_in[12]; const float* ab2 = (const float*)d_in[13];
    const float* aw3 = (const float*)d_in[14]; const float* ab3 = (const float*)d_in[15];
    const float* uw1 = (const float*)d_in[16]; const float* ub1 = (const float*)d_in[17];
    const float* uw2 = (const float*)d_in[18]; const float* ub2 = (const float*)d_in[19];
    const float* uw3 = (const float*)d_in[20]; const float* ub3 = (const float*)d_in[21];
    float* out = (float*)d_out;

    const int N = in_sizes[0] / 128;
    const int E = in_sizes[2];

    const int EDGE_SMEM = (64 * 272 + 64 * 256 + 8 * 256) * 4;   // 143360 B
    const int NODE_SMEM = (64 * 256 + 64 * 256 + 8 * 256) * 4;   // 139264 B
    cudaFuncSetAttribute(edge_kernel, cudaFuncAttributeMaxDynamicSharedMemorySize, EDGE_SMEM);
    cudaFuncSetAttribute(node_kernel, cudaFuncAttributeMaxDynamicSharedMemorySize, NODE_SMEM);

    // 1) init scratch
    {
        int total = N * 128;
        init_kernel<<<(total + 255) / 256, 256>>>(N);
    }
    // 2) edge + gate MLP
    {
        int blocks = (E + 63) / 64;
        edge_kernel<<<blocks, 256, EDGE_SMEM>>>(
            nodes, edges, senders, receivers,
            mw1, mb1, mw2, mb2, mw3, mb3,
            aw1, ab1, aw2, ab2, aw3, ab3, E);
    }
    // 3) softmax numerator + denom
    softmax_kernel<<<(E + 255) / 256, 256>>>(receivers, E);
    // 4) attention-weighted scatter
    {
        int warps_per_block = 8;
        int blocks = (E + warps_per_block - 1) / warps_per_block;
        aggr_kernel<<<blocks, 256>>>(receivers, E);
    }
    // 5) node update
    {
        int blocks = (N + 63) / 64;
        node_kernel<<<blocks, 256, NODE_SMEM>>>(
            nodes, uw1, ub1, uw2, ub2, uw3, ub3, out, N);
    }
}

// round 3
// speedup vs baseline: 1.6420x; 1.6420x over previous
#include <cuda_runtime.h>
#include <cuda_bf16.h>
#include <cstdint>

// Problem constants (shape-fixed per reference)
#define NMAX 50048
#define EMAX 400000

// Scratch (device globals: allocation-free rule)
__device__ float g_msgs[(size_t)EMAX * 128];
__device__ float g_gate[EMAX];
__device__ float g_wexp[EMAX];
__device__ int   g_segmax[NMAX];
__device__ float g_denom[NMAX];
__device__ float g_aggr[(size_t)NMAX * 128];

// ---------- float ordered-int encoding for atomicMax on floats ----------
__device__ __forceinline__ int f2ord(float f) {
    int i = __float_as_int(f);
    return (i >= 0) ? i : (i ^ 0x7fffffff);
}
__device__ __forceinline__ float ord2f(int o) {
    return __int_as_float((o >= 0) ? o : (o ^ 0x7fffffff));
}

// ---------- tf32 helpers ----------
__device__ __forceinline__ uint32_t f2tf32(float f) {
    uint32_t r;
    asm("cvt.rna.tf32.f32 %0, %1;" : "=r"(r) : "f"(f));
    return r;
}

__device__ __forceinline__ void mma_tf32(float c[4],
    uint32_t a0, uint32_t a1, uint32_t a2, uint32_t a3,
    uint32_t b0, uint32_t b1)
{
    asm volatile(
        "mma.sync.aligned.m16n8k8.row.col.f32.tf32.tf32.f32 "
        "{%0,%1,%2,%3}, {%4,%5,%6,%7}, {%8,%9}, {%0,%1,%2,%3};"
        : "+f"(c[0]), "+f"(c[1]), "+f"(c[2]), "+f"(c[3])
        : "r"(a0), "r"(a1), "r"(a2), "r"(a3), "r"(b0), "r"(b1));
}

// ---------------------------------------------------------------------------
// Tensor-core MLP layer over a 64-row tile.
//   sOut[64][NOUT] = act(sIn[64][K] @ W[K][NOUT] + B)
// 256 threads = 8 warps tiled 2(M: 32 rows each) x 4(N: NOUT/4 cols each).
// sIn/sOut hold tf32 bit patterns (valid fp32). Weights streamed through sW
// in 16-row K-slabs with tf32 conversion.
// Leading dims must satisfy ld % 32 in {4, 12, 20, 28} for conflict-free
// fragment loads (we use 276/260/132).
// If gOut != nullptr, full-fp32 results are also written to
// gOut[(row0_global + r) * NOUT + c] for rows with row0_global + r < row_limit.
// ---------------------------------------------------------------------------
template<int K, int NOUT, bool RELU, int LDIN, int LDOUT>
__device__ __forceinline__ void mma_layer(
    const uint32_t* __restrict__ sIn,
    const float* __restrict__ W, const float* __restrict__ Bv,
    uint32_t* __restrict__ sOut, uint32_t* __restrict__ sW,
    float* __restrict__ gOut, int row0_global, int row_limit)
{
    constexpr int NT  = NOUT / 32;   // n8-tiles per warp
    constexpr int LDW = NOUT + 4;    // LDW % 32 == 4  -> conflict-free B frags
    const int tid   = threadIdx.x;
    const int lane  = tid & 31;
    const int warp  = tid >> 5;
    const int mwarp = warp & 1;
    const int nwarp = warp >> 1;
    const int g     = lane >> 2;     // groupID
    const int tg    = lane & 3;      // threadID in group
    const int n_base = nwarp * (NOUT / 4);

    float acc[2][NT][4];
#pragma unroll
    for (int mt = 0; mt < 2; mt++)
#pragma unroll
        for (int nt = 0; nt < NT; nt++)
#pragma unroll
            for (int q = 0; q < 4; q++) acc[mt][nt][q] = 0.f;

    for (int kc = 0; kc < K; kc += 16) {
        __syncthreads();   // previous readers of sW are done
        // ---- stage W[kc..kc+15][0..NOUT) into sW as tf32 ----
        {
            constexpr int NV = 16 * NOUT / 4;           // float4 count
            const float4* src = (const float4*)(W + (size_t)kc * NOUT);
            for (int t = tid; t < NV; t += 256) {
                float4 w = __ldg(src + t);
                int row = t / (NOUT / 4);
                int cq  = t - row * (NOUT / 4);
                uint4 u = make_uint4(f2tf32(w.x), f2tf32(w.y),
                                     f2tf32(w.z), f2tf32(w.w));
                *(uint4*)(sW + row * LDW + cq * 4) = u;
            }
        }
        __syncthreads();
#pragma unroll
        for (int kk = 0; kk < 16; kk += 8) {
            // A fragments: 2 m16 tiles
            uint32_t a[2][4];
#pragma unroll
            for (int mt = 0; mt < 2; mt++) {
                int r0 = mwarp * 32 + mt * 16 + g;
                const uint32_t* p = sIn + r0 * LDIN + kc + kk + tg;
                a[mt][0] = p[0];
                a[mt][2] = p[4];
                const uint32_t* q = p + 8 * LDIN;
                a[mt][1] = q[0];
                a[mt][3] = q[4];
            }
            // B fragments: NT n8 tiles
            uint32_t b[NT][2];
#pragma unroll
            for (int nt = 0; nt < NT; nt++) {
                int c = n_base + nt * 8 + g;
                b[nt][0] = sW[(kk + tg) * LDW + c];
                b[nt][1] = sW[(kk + tg + 4) * LDW + c];
            }
#pragma unroll
            for (int mt = 0; mt < 2; mt++)
#pragma unroll
                for (int nt = 0; nt < NT; nt++)
                    mma_tf32(acc[mt][nt],
                             a[mt][0], a[mt][1], a[mt][2], a[mt][3],
                             b[nt][0], b[nt][1]);
        }
    }

    // ---- epilogue: bias (+relu), write tf32 to sOut, fp32 to gOut ----
#pragma unroll
    for (int nt = 0; nt < NT; nt++) {
        int c = n_base + nt * 8 + 2 * tg;
        float b0 = __ldg(Bv + c);
        float b1 = __ldg(Bv + c + 1);
#pragma unroll
        for (int mt = 0; mt < 2; mt++) {
#pragma unroll
            for (int h = 0; h < 2; h++) {
                int r = mwarp * 32 + mt * 16 + g + h * 8;
                float v0 = acc[mt][nt][h * 2 + 0] + b0;
                float v1 = acc[mt][nt][h * 2 + 1] + b1;
                if (RELU) { v0 = fmaxf(v0, 0.f); v1 = fmaxf(v1, 0.f); }
                *(uint2*)(sOut + r * LDOUT + c) =
                    make_uint2(f2tf32(v0), f2tf32(v1));
                if (gOut != nullptr && row0_global + r < row_limit)
                    *(float2*)(gOut + (size_t)(row0_global + r) * NOUT + c) =
                        make_float2(v0, v1);
            }
        }
    }
    __syncthreads();
}

// ---------------------------------------------------------------------------
// Kernel 1: init scratch
// ---------------------------------------------------------------------------
__global__ void init_kernel(int N) {
    int idx = blockIdx.x * blockDim.x + threadIdx.x;
    int total = N * 128;
    if (idx < total) g_aggr[idx] = 0.f;
    if (idx < N) {
        g_denom[idx] = 0.f;
        g_segmax[idx] = int(0x80000000);
    }
}

// ---------------------------------------------------------------------------
// Kernel 2: fused edge-MLP + gate-MLP on tensor cores. 64 edges / block.
// smem (uint32): sA[64*276] | sB[64*260] | sW[16*260]
// ---------------------------------------------------------------------------
__global__ __launch_bounds__(256, 1)
void edge_kernel(
    const float* __restrict__ nodes, const float* __restrict__ edges,
    const int* __restrict__ senders, const int* __restrict__ receivers,
    const float* __restrict__ w1, const float* __restrict__ b1,
    const float* __restrict__ w2, const float* __restrict__ b2,
    const float* __restrict__ w3, const float* __restrict__ b3,
    const float* __restrict__ aw1, const float* __restrict__ ab1,
    const float* __restrict__ aw2, const float* __restrict__ ab2,
    const float* __restrict__ aw3, const float* __restrict__ ab3,
    int E)
{
    extern __shared__ uint32_t smem[];
    uint32_t* sA = smem;               // 64*276
    uint32_t* sB = sA + 64 * 276;      // 64*260
    uint32_t* sW = sB + 64 * 260;      // 16*260

    const int tid  = threadIdx.x;
    const int lane = tid & 31;
    const int warp = tid >> 5;
    const int e0   = blockIdx.x * 64;

    // ---- gather feats = [edge(16) | nodes[s](128) | nodes[r](128)] as tf32 ----
#pragma unroll
    for (int i = 0; i < 8; i++) {
        int e = warp * 8 + i;
        int eg = e0 + e;
        int egc = eg < E ? eg : E - 1;
        int s = senders[egc];
        int r = receivers[egc];
        uint32_t* dst = sA + e * 276;
        if (lane < 4) {
            float4 v = *(const float4*)(edges + (size_t)egc * 16 + lane * 4);
            *(uint4*)(dst + lane * 4) =
                make_uint4(f2tf32(v.x), f2tf32(v.y), f2tf32(v.z), f2tf32(v.w));
        }
        float4 vs = *(const float4*)(nodes + (size_t)s * 128 + lane * 4);
        *(uint4*)(dst + 16 + lane * 4) =
            make_uint4(f2tf32(vs.x), f2tf32(vs.y), f2tf32(vs.z), f2tf32(vs.w));
        float4 vr = *(const float4*)(nodes + (size_t)r * 128 + lane * 4);
        *(uint4*)(dst + 144 + lane * 4) =
            make_uint4(f2tf32(vr.x), f2tf32(vr.y), f2tf32(vr.z), f2tf32(vr.w));
    }
    // (mma_layer's first __syncthreads orders the gather before reads)

    // ---- message MLP ----
    mma_layer<272, 256, true , 276, 260>(sA, w1, b1, sB, sW, nullptr, 0, 0);
    mma_layer<256, 256, false, 260, 260>(sB, w2, b2, sA, sW, nullptr, 0, 0);
    mma_layer<256, 128, false, 260, 132>(sA, w3, b3, sB, sW, g_msgs, e0, E);

    // ---- gate MLP ----
    mma_layer<128, 128, true , 132, 132>(sB, aw1, ab1, sA, sW, nullptr, 0, 0);
    mma_layer<128, 128, false, 132, 132>(sA, aw2, ab2, sB, sW, nullptr, 0, 0);

    // gate = g2 @ aw3 + ab3  (128 -> 1), one warp per 8 edges
    const float* sBf = (const float*)sB;
#pragma unroll
    for (int i = 0; i < 8; i++) {
        int e = warp * 8 + i;
        float p = 0.f;
#pragma unroll
        for (int j = 0; j < 4; j++)
            p += sBf[e * 132 + lane + 32 * j] * __ldg(aw3 + lane + 32 * j);
#pragma unroll
        for (int off = 16; off > 0; off >>= 1)
            p += __shfl_xor_sync(0xffffffffu, p, off);
        if (lane == 0) {
            int eg = e0 + e;
            if (eg < E) {
                float gate = p + __ldg(ab3);
                g_gate[eg] = gate;
                int r = receivers[eg];
                atomicMax(&g_segmax[r], f2ord(gate));
            }
        }
    }
}

// ---------------------------------------------------------------------------
// Kernel 3: w = exp(gate - segmax[recv]); denom[recv] += w
// ---------------------------------------------------------------------------
__global__ void softmax_kernel(const int* __restrict__ receivers, int E) {
    int e = blockIdx.x * blockDim.x + threadIdx.x;
    if (e >= E) return;
    int r = receivers[e];
    float m = ord2f(g_segmax[r]);
    float w = expf(g_gate[e] - m);
    g_wexp[e] = w;
    atomicAdd(&g_denom[r], w);
}

// ---------------------------------------------------------------------------
// Kernel 4: aggr[recv] += (w/denom[recv]) * msgs[e]   (warp per edge)
// ---------------------------------------------------------------------------
__global__ __launch_bounds__(256)
void aggr_kernel(const int* __restrict__ receivers, int E) {
    int warp = (blockIdx.x * blockDim.x + threadIdx.x) >> 5;
    int lane = threadIdx.x & 31;
    if (warp >= E) return;
    int r = receivers[warp];
    float attn = g_wexp[warp] / g_denom[r];
    float4 v = *(const float4*)(g_msgs + (size_t)warp * 128 + lane * 4);
    float* dst = g_aggr + (size_t)r * 128 + lane * 4;
    atomicAdd(dst + 0, attn * v.x);
    atomicAdd(dst + 1, attn * v.y);
    atomicAdd(dst + 2, attn * v.z);
    atomicAdd(dst + 3, attn * v.w);
}

// ---------------------------------------------------------------------------
// Kernel 5: node update MLP on tensor cores. 64 nodes / block.
// smem (uint32): sA[64*260] | sB[64*260] | sW[16*260]
// ---------------------------------------------------------------------------
__global__ __launch_bounds__(256, 1)
void node_kernel(
    const float* __restrict__ nodes,
    const float* __restrict__ uw1, const float* __restrict__ ub1,
    const float* __restrict__ uw2, const float* __restrict__ ub2,
    const float* __restrict__ uw3, const float* __restrict__ ub3,
    float* __restrict__ out, int N)
{
    extern __shared__ uint32_t smem[];
    uint32_t* sA = smem;               // 64*260
    uint32_t* sB = sA + 64 * 260;      // 64*260
    uint32_t* sW = sB + 64 * 260;      // 16*260

    const int tid  = threadIdx.x;
    const int lane = tid & 31;
    const int warp = tid >> 5;
    const int n0   = blockIdx.x * 64;

    // gather u = [node(128) | aggr(128)] as tf32
#pragma unroll
    for (int i = 0; i < 8; i++) {
        int e = warp * 8 + i;
        int n = n0 + e;
        uint32_t* dst = sA + e * 260;
        if (n < N) {
            float4 v0 = *(const float4*)(nodes + (size_t)n * 128 + lane * 4);
            *(uint4*)(dst + lane * 4) =
                make_uint4(f2tf32(v0.x), f2tf32(v0.y), f2tf32(v0.z), f2tf32(v0.w));
            float4 v1 = *(const float4*)(g_aggr + (size_t)n * 128 + lane * 4);
            *(uint4*)(dst + 128 + lane * 4) =
                make_uint4(f2tf32(v1.x), f2tf32(v1.y), f2tf32(v1.z), f2tf32(v1.w));
        } else {
            uint4 z = make_uint4(0u, 0u, 0u, 0u);
            *(uint4*)(dst + lane * 4) = z;
            *(uint4*)(dst + 128 + lane * 4) = z;
        }
    }

    mma_layer<256, 256, true , 260, 260>(sA, uw1, ub1, sB, sW, nullptr, 0, 0);
    mma_layer<256, 256, false, 260, 260>(sB, uw2, ub2, sA, sW, nullptr, 0, 0);
    mma_layer<256, 128, false, 260, 132>(sA, uw3, ub3, sB, sW, out, n0, N);
}

// ---------------------------------------------------------------------------
extern "C" void kernel_launch(void* const* d_in, const int* in_sizes, int n_in,
                              void* d_out, int out_size)
{
    const float* nodes     = (const float*)d_in[0];
    const float* edges     = (const float*)d_in[1];
    const int*   senders   = (const int*)  d_in[2];
    const int*   receivers = (const int*)  d_in[3];
    const float* mw1 = (const float*)d_in[4];  const float* mb1 = (const float*)d_in[5];
    const float* mw2 = (const float*)d_in[6];  const float* mb2 = (const float*)d_in[7];
    const float* mw3 = (const float*)d_in[8];  const float* mb3 = (const float*)d_in[9];
    const float* aw1 = (const float*)d_in[10]; const float* ab1 = (const float*)d_in[11];
    const float* aw2 = (const float*)d_in[12]; const float* ab2 = (const float*)d_in[13];
    const float* aw3 = (const float*)d_in[14]; const float* ab3 = (const float*)d_in[15];
    const float* uw1 = (const float*)d_in[16]; const float* ub1 = (const float*)d_in[17];
    const float* uw2 = (const float*)d_in[18]; const float* ub2 = (const float*)d_in[19];
    const float* uw3 = (const float*)d_in[20]; const float* ub3 = (const float*)d_in[21];
    float* out = (float*)d_out;

    const int N = in_sizes[0] / 128;
    const int E = in_sizes[2];

    const int EDGE_SMEM = (64 * 276 + 64 * 260 + 16 * 260) * 4;  // 153856 B
    const int NODE_SMEM = (64 * 260 + 64 * 260 + 16 * 260) * 4;  // 149760 B
    static bool attr_done = false;
    if (!attr_done) {
        cudaFuncSetAttribute(edge_kernel, cudaFuncAttributeMaxDynamicSharedMemorySize, EDGE_SMEM);
        cudaFuncSetAttribute(node_kernel, cudaFuncAttributeMaxDynamicSharedMemorySize, NODE_SMEM);
        attr_done = true;
    }

    // 1) init scratch
    {
        int total = N * 128;
        init_kernel<<<(total + 255) / 256, 256>>>(N);
    }
    // 2) edge + gate MLP (tensor cores)
    {
        int blocks = (E + 63) / 64;
        edge_kernel<<<blocks, 256, EDGE_SMEM>>>(
            nodes, edges, senders, receivers,
            mw1, mb1, mw2, mb2, mw3, mb3,
            aw1, ab1, aw2, ab2, aw3, ab3, E);
    }
    // 3) softmax numerator + denom
    softmax_kernel<<<(E + 255) / 256, 256>>>(receivers, E);
    // 4) attention-weighted scatter
    {
        int blocks = (E + 7) / 8;
        aggr_kernel<<<blocks, 256>>>(receivers, E);
    }
    // 5) node update (tensor cores)
    {
        int blocks = (N + 63) / 64;
        node_kernel<<<blocks, 256, NODE_SMEM>>>(
            nodes, uw1, ub1, uw2, ub2, uw3, ub3, out, N);
    }
}

// round 4
// speedup vs baseline: 2.6802x; 1.6323x over previous
#include <cuda_runtime.h>
#include <cuda_bf16.h>
#include <cstdint>

// Problem constants (shape-fixed per reference)
#define NMAX 50048
#define EMAX 400000

// Scratch (device globals: allocation-free rule)
__device__ float g_msgs[(size_t)EMAX * 128];
__device__ float g_gate[EMAX];
__device__ float g_wexp[EMAX];
__device__ int   g_segmax[NMAX];
__device__ float g_denom[NMAX];
__device__ float g_aggr[(size_t)NMAX * 128];

// ---------- float ordered-int encoding for atomicMax on floats ----------
__device__ __forceinline__ int f2ord(float f) {
    int i = __float_as_int(f);
    return (i >= 0) ? i : (i ^ 0x7fffffff);
}
__device__ __forceinline__ float ord2f(int o) {
    return __int_as_float((o >= 0) ? o : (o ^ 0x7fffffff));
}

// ---------- tf32 helpers ----------
__device__ __forceinline__ uint32_t f2tf32(float f) {
    uint32_t r;
    asm("cvt.rna.tf32.f32 %0, %1;" : "=r"(r) : "f"(f));
    return r;
}

__device__ __forceinline__ void mma_tf32(float c[4],
    uint32_t a0, uint32_t a1, uint32_t a2, uint32_t a3,
    uint32_t b0, uint32_t b1)
{
    asm volatile(
        "mma.sync.aligned.m16n8k8.row.col.f32.tf32.tf32.f32 "
        "{%0,%1,%2,%3}, {%4,%5,%6,%7}, {%8,%9}, {%0,%1,%2,%3};"
        : "+f"(c[0]), "+f"(c[1]), "+f"(c[2]), "+f"(c[3])
        : "r"(a0), "r"(a1), "r"(a2), "r"(a3), "r"(b0), "r"(b1));
}

__device__ __forceinline__ uint32_t smem_u32(const void* p) {
    return (uint32_t)__cvta_generic_to_shared(p);
}

// Weight double-buffer stride (words): 16 rows x max LDW (256+4)
#define SW_BUF 4160

// ---------------------------------------------------------------------------
// Tensor-core MLP layer over a 64-row tile, cp.async-pipelined weights.
//   sOut[64][NOUT] = act(sIn[64][K] @ W[K][NOUT] + B)
// 256 threads = 8 warps tiled 2(M: 32 rows) x 4(N: NOUT/4 cols).
// sIn/sOut hold fp32; cvt to tf32 happens at fragment load.
// Weights stream via cp.async into sW[2][16][LDW], double-buffered:
// slab s+1 is in flight while slab s computes.
// LDIN/LDOUT % 32 == 20 or 4; LDW = NOUT+4 (% 32 == 4): conflict-free LDS.
// ---------------------------------------------------------------------------
template<int K, int NOUT, bool RELU, int LDIN, int LDOUT>
__device__ __forceinline__ void mma_layer(
    const float* __restrict__ sIn,
    const float* __restrict__ W, const float* __restrict__ Bv,
    float* __restrict__ sOut, float* __restrict__ sW,
    float* __restrict__ gOut, int row0_global, int row_limit)
{
    constexpr int NT    = NOUT / 32;   // n8-tiles per warp
    constexpr int LDW   = NOUT + 4;
    constexpr int NSLAB = K / 16;      // K is a multiple of 16 everywhere
    constexpr int CH    = 16 * NOUT / 4;   // 16B chunks per slab
    constexpr int CPR   = NOUT / 4;        // chunks per row (power of two)

    const int tid   = threadIdx.x;
    const int lane  = tid & 31;
    const int warp  = tid >> 5;
    const int mwarp = warp & 1;
    const int nwarp = warp >> 1;
    const int g     = lane >> 2;
    const int tg    = lane & 3;
    const int n_base = nwarp * (NOUT / 4);

    // issue cp.async for weight slab s into buffer buf
    auto issue = [&](int s, int buf) {
        const float* src0 = W + (size_t)s * 16 * NOUT;
        float* dst0 = sW + buf * SW_BUF;
#pragma unroll
        for (int c = tid; c < CH; c += 256) {
            int row = c / CPR;
            int off = (c - row * CPR) * 4;
            uint32_t daddr = smem_u32(dst0 + row * LDW + off);
            asm volatile("cp.async.ca.shared.global [%0], [%1], 16;"
                         :: "r"(daddr), "l"(src0 + row * NOUT + off));
        }
        asm volatile("cp.async.commit_group;");
    };

    float acc[2][NT][4];
#pragma unroll
    for (int mt = 0; mt < 2; mt++)
#pragma unroll
        for (int nt = 0; nt < NT; nt++)
#pragma unroll
            for (int q = 0; q < 4; q++) acc[mt][nt][q] = 0.f;

    // prologue: 2 slabs in flight
    issue(0, 0);
    if (NSLAB > 1) issue(1, 1);

    for (int s = 0; s < NSLAB; s++) {
        if (s + 1 < NSLAB)
            asm volatile("cp.async.wait_group 1;" ::: "memory");
        else
            asm volatile("cp.async.wait_group 0;" ::: "memory");
        __syncthreads();   // weights for slab s visible to all; also orders sIn

        const float* buf = sW + (s & 1) * SW_BUF;
        const int kc = s * 16;
#pragma unroll
        for (int kk = 0; kk < 16; kk += 8) {
            uint32_t a[2][4];
#pragma unroll
            for (int mt = 0; mt < 2; mt++) {
                int r0 = mwarp * 32 + mt * 16 + g;
                const float* p = sIn + r0 * LDIN + kc + kk + tg;
                a[mt][0] = f2tf32(p[0]);
                a[mt][2] = f2tf32(p[4]);
                const float* q = p + 8 * LDIN;
                a[mt][1] = f2tf32(q[0]);
                a[mt][3] = f2tf32(q[4]);
            }
            uint32_t b[NT][2];
#pragma unroll
            for (int nt = 0; nt < NT; nt++) {
                int c = n_base + nt * 8 + g;
                b[nt][0] = f2tf32(buf[(kk + tg) * LDW + c]);
                b[nt][1] = f2tf32(buf[(kk + tg + 4) * LDW + c]);
            }
#pragma unroll
            for (int mt = 0; mt < 2; mt++)
#pragma unroll
                for (int nt = 0; nt < NT; nt++)
                    mma_tf32(acc[mt][nt],
                             a[mt][0], a[mt][1], a[mt][2], a[mt][3],
                             b[nt][0], b[nt][1]);
        }

        if (s + 2 < NSLAB) {
            __syncthreads();          // all reads of buf (s&1) done
            issue(s + 2, s & 1);      // refill it
        }
    }

    // ---- epilogue: bias (+relu), fp32 to sOut (and gOut) ----
#pragma unroll
    for (int nt = 0; nt < NT; nt++) {
        int c = n_base + nt * 8 + 2 * tg;
        float b0 = __ldg(Bv + c);
        float b1 = __ldg(Bv + c + 1);
#pragma unroll
        for (int mt = 0; mt < 2; mt++) {
#pragma unroll
            for (int h = 0; h < 2; h++) {
                int r = mwarp * 32 + mt * 16 + g + h * 8;
                float v0 = acc[mt][nt][h * 2 + 0] + b0;
                float v1 = acc[mt][nt][h * 2 + 1] + b1;
                if (RELU) { v0 = fmaxf(v0, 0.f); v1 = fmaxf(v1, 0.f); }
                *(float2*)(sOut + r * LDOUT + c) = make_float2(v0, v1);
                if (gOut != nullptr && row0_global + r < row_limit)
                    *(float2*)(gOut + (size_t)(row0_global + r) * NOUT + c) =
                        make_float2(v0, v1);
            }
        }
    }
    __syncthreads();   // sOut complete; sW free for next layer
}

// ---------------------------------------------------------------------------
// Kernel 1: init scratch
// ---------------------------------------------------------------------------
__global__ void init_kernel(int N) {
    int idx = blockIdx.x * blockDim.x + threadIdx.x;
    int total = N * 128;
    if (idx < total) g_aggr[idx] = 0.f;
    if (idx < N) {
        g_denom[idx] = 0.f;
        g_segmax[idx] = int(0x80000000);
    }
}

// ---------------------------------------------------------------------------
// Kernel 2: fused edge-MLP + gate-MLP. 64 edges / block.
// smem (floats): sA[64*276] | sB[64*260] | sW[2*SW_BUF]
// ---------------------------------------------------------------------------
__global__ __launch_bounds__(256, 1)
void edge_kernel(
    const float* __restrict__ nodes, const float* __restrict__ edges,
    const int* __restrict__ senders, const int* __restrict__ receivers,
    const float* __restrict__ w1, const float* __restrict__ b1,
    const float* __restrict__ w2, const float* __restrict__ b2,
    const float* __restrict__ w3, const float* __restrict__ b3,
    const float* __restrict__ aw1, const float* __restrict__ ab1,
    const float* __restrict__ aw2, const float* __restrict__ ab2,
    const float* __restrict__ aw3, const float* __restrict__ ab3,
    int E)
{
    extern __shared__ float smem[];
    float* sA = smem;                 // 64*276
    float* sB = sA + 64 * 276;        // 64*260
    float* sW = sB + 64 * 260;        // 2*SW_BUF

    const int tid  = threadIdx.x;
    const int lane = tid & 31;
    const int warp = tid >> 5;
    const int e0   = blockIdx.x * 64;

    // ---- gather feats = [edge(16) | nodes[s](128) | nodes[r](128)] (fp32) ----
#pragma unroll
    for (int i = 0; i < 8; i++) {
        int e = warp * 8 + i;
        int eg = e0 + e;
        int egc = eg < E ? eg : E - 1;
        int s = senders[egc];
        int r = receivers[egc];
        float* dst = sA + e * 276;
        if (lane < 4)
            *(float4*)(dst + lane * 4) = *(const float4*)(edges + (size_t)egc * 16 + lane * 4);
        *(float4*)(dst + 16 + lane * 4)  = *(const float4*)(nodes + (size_t)s * 128 + lane * 4);
        *(float4*)(dst + 144 + lane * 4) = *(const float4*)(nodes + (size_t)r * 128 + lane * 4);
    }
    // (first sync inside mma_layer orders the gather)

    // ---- message MLP ----
    mma_layer<272, 256, true , 276, 260>(sA, w1, b1, sB, sW, nullptr, 0, 0);
    mma_layer<256, 256, false, 260, 260>(sB, w2, b2, sA, sW, nullptr, 0, 0);
    mma_layer<256, 128, false, 260, 132>(sA, w3, b3, sB, sW, g_msgs, e0, E);

    // ---- gate MLP ----
    mma_layer<128, 128, true , 132, 132>(sB, aw1, ab1, sA, sW, nullptr, 0, 0);
    mma_layer<128, 128, false, 132, 132>(sA, aw2, ab2, sB, sW, nullptr, 0, 0);

    // gate = g2 @ aw3 + ab3  (128 -> 1), one warp per 8 edges
#pragma unroll
    for (int i = 0; i < 8; i++) {
        int e = warp * 8 + i;
        float p = 0.f;
#pragma unroll
        for (int j = 0; j < 4; j++)
            p += sB[e * 132 + lane + 32 * j] * __ldg(aw3 + lane + 32 * j);
#pragma unroll
        for (int off = 16; off > 0; off >>= 1)
            p += __shfl_xor_sync(0xffffffffu, p, off);
        if (lane == 0) {
            int eg = e0 + e;
            if (eg < E) {
                float gate = p + __ldg(ab3);
                g_gate[eg] = gate;
                int r = receivers[eg];
                atomicMax(&g_segmax[r], f2ord(gate));
            }
        }
    }
}

// ---------------------------------------------------------------------------
// Kernel 3: w = exp(gate - segmax[recv]); denom[recv] += w
// ---------------------------------------------------------------------------
__global__ void softmax_kernel(const int* __restrict__ receivers, int E) {
    int e = blockIdx.x * blockDim.x + threadIdx.x;
    if (e >= E) return;
    int r = receivers[e];
    float m = ord2f(g_segmax[r]);
    float w = expf(g_gate[e] - m);
    g_wexp[e] = w;
    atomicAdd(&g_denom[r], w);
}

// ---------------------------------------------------------------------------
// Kernel 4: aggr[recv] += (w/denom[recv]) * msgs[e]   (warp per edge)
// ---------------------------------------------------------------------------
__global__ __launch_bounds__(256)
void aggr_kernel(const int* __restrict__ receivers, int E) {
    int warp = (blockIdx.x * blockDim.x + threadIdx.x) >> 5;
    int lane = threadIdx.x & 31;
    if (warp >= E) return;
    int r = receivers[warp];
    float attn = g_wexp[warp] / g_denom[r];
    float4 v = *(const float4*)(g_msgs + (size_t)warp * 128 + lane * 4);
    float* dst = g_aggr + (size_t)r * 128 + lane * 4;
    atomicAdd(dst + 0, attn * v.x);
    atomicAdd(dst + 1, attn * v.y);
    atomicAdd(dst + 2, attn * v.z);
    atomicAdd(dst + 3, attn * v.w);
}

// ---------------------------------------------------------------------------
// Kernel 5: node update MLP. 64 nodes / block.
// smem (floats): sA[64*260] | sB[64*260] | sW[2*SW_BUF]
// ---------------------------------------------------------------------------
__global__ __launch_bounds__(256, 1)
void node_kernel(
    const float* __restrict__ nodes,
    const float* __restrict__ uw1, const float* __restrict__ ub1,
    const float* __restrict__ uw2, const float* __restrict__ ub2,
    const float* __restrict__ uw3, const float* __restrict__ ub3,
    float* __restrict__ out, int N)
{
    extern __shared__ float smem[];
    float* sA = smem;                 // 64*260
    float* sB = sA + 64 * 260;        // 64*260
    float* sW = sB + 64 * 260;        // 2*SW_BUF

    const int tid  = threadIdx.x;
    const int lane = tid & 31;
    const int warp = tid >> 5;
    const int n0   = blockIdx.x * 64;

    // gather u = [node(128) | aggr(128)] (fp32)
#pragma unroll
    for (int i = 0; i < 8; i++) {
        int e = warp * 8 + i;
        int n = n0 + e;
        float* dst = sA + e * 260;
        if (n < N) {
            *(float4*)(dst + lane * 4)       = *(const float4*)(nodes + (size_t)n * 128 + lane * 4);
            *(float4*)(dst + 128 + lane * 4) = *(const float4*)(g_aggr + (size_t)n * 128 + lane * 4);
        } else {
            float4 z = make_float4(0.f, 0.f, 0.f, 0.f);
            *(float4*)(dst + lane * 4) = z;
            *(float4*)(dst + 128 + lane * 4) = z;
        }
    }

    mma_layer<256, 256, true , 260, 260>(sA, uw1, ub1, sB, sW, nullptr, 0, 0);
    mma_layer<256, 256, false, 260, 260>(sB, uw2, ub2, sA, sW, nullptr, 0, 0);
    mma_layer<256, 128, false, 260, 132>(sA, uw3, ub3, sB, sW, out, n0, N);
}

// ---------------------------------------------------------------------------
extern "C" void kernel_launch(void* const* d_in, const int* in_sizes, int n_in,
                              void* d_out, int out_size)
{
    const float* nodes     = (const float*)d_in[0];
    const float* edges     = (const float*)d_in[1];
    const int*   senders   = (const int*)  d_in[2];
    const int*   receivers = (const int*)  d_in[3];
    const float* mw1 = (const float*)d_in[4];  const float* mb1 = (const float*)d_in[5];
    const float* mw2 = (const float*)d_in[6];  const float* mb2 = (const float*)d_in[7];
    const float* mw3 = (const float*)d_in[8];  const float* mb3 = (const float*)d_in[9];
    const float* aw1 = (const float*)d_in[10]; const float* ab1 = (const float*)d_in[11];
    const float* aw2 = (const float*)d_in[12]; const float* ab2 = (const float*)d_in[13];
    const float* aw3 = (const float*)d_in[14]; const float* ab3 = (const float*)d_in[15];
    const float* uw1 = (const float*)d_in[16]; const float* ub1 = (const float*)d_in[17];
    const float* uw2 = (const float*)d_in[18]; const float* ub2 = (const float*)d_in[19];
    const float* uw3 = (const float*)d_in[20]; const float* ub3 = (const float*)d_in[21];
    float* out = (float*)d_out;

    const int N = in_sizes[0] / 128;
    const int E = in_sizes[2];

    const int EDGE_SMEM = (64 * 276 + 64 * 260 + 2 * SW_BUF) * 4;  // 170496 B
    const int NODE_SMEM = (64 * 260 + 64 * 260 + 2 * SW_BUF) * 4;  // 166400 B
    cudaFuncSetAttribute(edge_kernel, cudaFuncAttributeMaxDynamicSharedMemorySize, EDGE_SMEM);
    cudaFuncSetAttribute(node_kernel, cudaFuncAttributeMaxDynamicSharedMemorySize, NODE_SMEM);

    // 1) init scratch
    {
        int total = N * 128;
        init_kernel<<<(total + 255) / 256, 256>>>(N);
    }
    // 2) edge + gate MLP (tensor cores, cp.async pipelined)
    {
        int blocks = (E + 63) / 64;
        edge_kernel<<<blocks, 256, EDGE_SMEM>>>(
            nodes, edges, senders, receivers,
            mw1, mb1, mw2, mb2, mw3, mb3,
            aw1, ab1, aw2, ab2, aw3, ab3, E);
    }
    // 3) softmax numerator + denom
    softmax_kernel<<<(E + 255) / 256, 256>>>(receivers, E);
    // 4) attention-weighted scatter
    {
        int blocks = (E + 7) / 8;
        aggr_kernel<<<blocks, 256>>>(receivers, E);
    }
    // 5) node update (tensor cores, cp.async pipelined)
    {
        int blocks = (N + 63) / 64;
        node_kernel<<<blocks, 256, NODE_SMEM>>>(
            nodes, uw1, ub1, uw2, ub2, uw3, ub3, out, N);
    }
}